// round 12
// baseline (speedup 1.0000x reference)
#include <cuda_runtime.h>
#include <cuda_bf16.h>
#include <cstdint>

#define T_STEPS 2048
#define BATCH   16
#define DIM     1024
#define NDIM    64
#define NTOT    256
#define MROWS   (T_STEPS * BATCH)   // 32768
#define NCHUNKS (T_STEPS / 8)       // 256

// ---------------- static device scratch ----------------
__device__ __nv_bfloat16 g_Ah[MROWS * DIM];
__device__ __nv_bfloat16 g_Al[MROWS * DIM];
__device__ __nv_bfloat16 g_Bh[NTOT * DIM];    // [n][k]
__device__ __nv_bfloat16 g_Bl[NTOT * DIM];
__device__ float g_P[MROWS * NTOT];           // [t*B+b][k|v|q|a]
__device__ float g_C[MROWS];                  // C_t = k_{t-1}.k_t per (t,b)
__device__ float2 g_AW[MROWS * NDIM];         // (alpha, w) per (t,b,row)
__device__ float g_CP[NCHUNKS * BATCH * NDIM * NDIM];  // S checkpoint per chunk

// ---------------- PTX helpers (baseline ISA only) ----------------
__device__ __forceinline__ uint32_t smem_u32(const void* p) {
    return (uint32_t)__cvta_generic_to_shared(p);
}
__device__ __forceinline__ void cpa16(uint32_t sa, const void* g) {
    asm volatile("cp.async.cg.shared.global [%0], [%1], 16;" :: "r"(sa), "l"(g) : "memory");
}
__device__ __forceinline__ void cpa8(uint32_t sa, const void* g) {
    asm volatile("cp.async.ca.shared.global [%0], [%1], 8;" :: "r"(sa), "l"(g) : "memory");
}
__device__ __forceinline__ void cp_commit() {
    asm volatile("cp.async.commit_group;" ::: "memory");
}
template<int N>
__device__ __forceinline__ void cp_wait() {
    asm volatile("cp.async.wait_group %0;" :: "n"(N) : "memory");
}
__device__ __forceinline__ void ldm_x4(uint32_t& r0, uint32_t& r1, uint32_t& r2, uint32_t& r3,
                                       uint32_t addr) {
    asm volatile("ldmatrix.sync.aligned.m8n8.x4.shared.b16 {%0,%1,%2,%3}, [%4];"
                 : "=r"(r0), "=r"(r1), "=r"(r2), "=r"(r3) : "r"(addr));
}
__device__ __forceinline__ void mma_bf16(float* c, const uint32_t* a, const uint32_t* b) {
    asm volatile("mma.sync.aligned.m16n8k16.row.col.f32.bf16.bf16.f32 "
                 "{%0,%1,%2,%3}, {%4,%5,%6,%7}, {%8,%9}, {%0,%1,%2,%3};"
                 : "+f"(c[0]), "+f"(c[1]), "+f"(c[2]), "+f"(c[3])
                 : "r"(a[0]), "r"(a[1]), "r"(a[2]), "r"(a[3]), "r"(b[0]), "r"(b[1]));
}

// packed f32x2
typedef unsigned long long ull;
__device__ __forceinline__ ull pack2(float lo, float hi) {
    ull r; asm("mov.b64 %0, {%1, %2};" : "=l"(r) : "f"(lo), "f"(hi)); return r;
}
__device__ __forceinline__ void unpack2(ull v, float& lo, float& hi) {
    asm("mov.b64 {%0, %1}, %2;" : "=f"(lo), "=f"(hi) : "l"(v));
}
__device__ __forceinline__ ull fma2g(ull a, ull b, ull c) {
    ull d; asm("fma.rn.f32x2 %0, %1, %2, %3;" : "=l"(d) : "l"(a), "l"(b), "l"(c)); return d;
}
__device__ __forceinline__ ull mul2(ull a, ull b) {
    ull d; asm("mul.rn.f32x2 %0, %1, %2;" : "=l"(d) : "l"(a), "l"(b)); return d;
}

__device__ __forceinline__ void split_bf16(float x, __nv_bfloat16& h, __nv_bfloat16& l) {
    h = __float2bfloat16(x);
    l = __float2bfloat16(x - __bfloat162float(h));
}

// ---------------- prep kernels ----------------
__global__ void convert_x(const float* __restrict__ x) {
    const int total4 = MROWS * DIM / 4;
    for (int i = blockIdx.x * blockDim.x + threadIdx.x; i < total4;
         i += gridDim.x * blockDim.x) {
        float4 v = ((const float4*)x)[i];
        __nv_bfloat16 h0, h1, h2, h3, l0, l1, l2, l3;
        split_bf16(v.x, h0, l0); split_bf16(v.y, h1, l1);
        split_bf16(v.z, h2, l2); split_bf16(v.w, h3, l3);
        ((__nv_bfloat162*)g_Ah)[2 * i + 0] = __nv_bfloat162(h0, h1);
        ((__nv_bfloat162*)g_Ah)[2 * i + 1] = __nv_bfloat162(h2, h3);
        ((__nv_bfloat162*)g_Al)[2 * i + 0] = __nv_bfloat162(l0, l1);
        ((__nv_bfloat162*)g_Al)[2 * i + 1] = __nv_bfloat162(l2, l3);
    }
}

__global__ void convert_w(const float* __restrict__ Wk, const float* __restrict__ Wv,
                          const float* __restrict__ Wq, const float* __restrict__ Wa) {
    int n = blockIdx.x;
    int g = n >> 6, r = n & 63;
    const float* W = (g == 0) ? Wk : (g == 1) ? Wv : (g == 2) ? Wq : Wa;
    for (int d = threadIdx.x; d < DIM; d += blockDim.x) {
        __nv_bfloat16 h, l;
        split_bf16(W[r * DIM + d], h, l);
        g_Bh[n * DIM + d] = h;
        g_Bl[n * DIM + d] = l;
    }
}

// ---------------- mma.sync GEMM (unchanged) ----------------
#define BM 128
#define BN 128
#define BK 32
#define LDP 40
#define KT (DIM / BK)
#define NSTAGE 3
#define STAGE_ELE (4 * 128 * LDP)

__device__ __forceinline__ uint32_t soff(int stage, int arr, int row, int col) {
    return (uint32_t)(((stage * STAGE_ELE) + ((arr * 128 + row) * LDP) + col) * 2);
}

__global__ __launch_bounds__(256, 1) void gemm_mma(int unused) {
    extern __shared__ __nv_bfloat16 smem[];
    const uint32_t sbase = smem_u32(smem);

    const int m0 = blockIdx.y * BM;
    const int n0 = blockIdx.x * BN;
    const int tid = threadIdx.x;
    const int wid = tid >> 5;
    const int lane = tid & 31;
    const int warp_m = (wid & 3) * 32;
    const int warp_n = (wid >> 2) * 64;

    float acc[2][8][4];
    #pragma unroll
    for (int i = 0; i < 2; i++)
        #pragma unroll
        for (int j = 0; j < 8; j++)
            #pragma unroll
            for (int r = 0; r < 4; r++) acc[i][j][r] = 0.f;

    const int lm = lane >> 3;
    const int arow = (lm & 1) * 8 + (lane & 7);
    const int akc  = (lm >> 1) * 8;
    const int bnof = (lm >> 1) * 8 + (lane & 7);
    const int bkc  = (lm & 1) * 8;

    auto load_stage = [&](int stage, int kt) {
        const int k0 = kt * BK;
        #pragma unroll
        for (int arr = 0; arr < 4; arr++) {
            const __nv_bfloat16* gb = (arr == 0) ? g_Ah : (arr == 1) ? g_Al
                                   : (arr == 2) ? g_Bh : g_Bl;
            const int rbase = (arr < 2) ? m0 : n0;
            #pragma unroll
            for (int h = 0; h < 2; h++) {
                int cl = h * 256 + tid;
                int row = cl >> 2;
                int seg = cl & 3;
                cpa16(sbase + soff(stage, arr, row, seg * 8),
                      gb + (size_t)(rbase + row) * DIM + k0 + seg * 8);
            }
        }
        cp_commit();
    };

    load_stage(0, 0);
    load_stage(1, 1);

    int cur = 0;
    for (int kt = 0; kt < KT; ++kt) {
        if (kt + 2 < KT) {
            load_stage((kt + 2) % NSTAGE, kt + 2);
            cp_wait<2>();
        } else if (kt + 1 < KT) {
            cp_wait<1>();
        } else {
            cp_wait<0>();
        }
        __syncthreads();

        #pragma unroll
        for (int kk = 0; kk < BK; kk += 16) {
            uint32_t ah[2][4], al[2][4], bh[8][2], bl[8][2];
            #pragma unroll
            for (int mi = 0; mi < 2; mi++) {
                ldm_x4(ah[mi][0], ah[mi][1], ah[mi][2], ah[mi][3],
                       sbase + soff(cur, 0, warp_m + mi * 16 + arow, kk + akc));
                ldm_x4(al[mi][0], al[mi][1], al[mi][2], al[mi][3],
                       sbase + soff(cur, 1, warp_m + mi * 16 + arow, kk + akc));
            }
            #pragma unroll
            for (int p = 0; p < 4; p++) {
                ldm_x4(bh[2 * p][0], bh[2 * p][1], bh[2 * p + 1][0], bh[2 * p + 1][1],
                       sbase + soff(cur, 2, warp_n + p * 16 + bnof, kk + bkc));
                ldm_x4(bl[2 * p][0], bl[2 * p][1], bl[2 * p + 1][0], bl[2 * p + 1][1],
                       sbase + soff(cur, 3, warp_n + p * 16 + bnof, kk + bkc));
            }
            #pragma unroll
            for (int mi = 0; mi < 2; mi++)
                #pragma unroll
                for (int nb = 0; nb < 8; nb++) {
                    mma_bf16(acc[mi][nb], ah[mi], bh[nb]);
                    mma_bf16(acc[mi][nb], ah[mi], bl[nb]);
                    mma_bf16(acc[mi][nb], al[mi], bh[nb]);
                }
        }
        __syncthreads();
        cur = (cur + 1) % NSTAGE;
    }

    const int cr = lane >> 2;
    const int cc = (lane & 3) * 2;
    #pragma unroll
    for (int mi = 0; mi < 2; mi++) {
        #pragma unroll
        for (int nb = 0; nb < 8; nb++) {
            int row = m0 + warp_m + mi * 16 + cr;
            int col = n0 + warp_n + nb * 8 + cc;
            *(float2*)&g_P[(size_t)row * NTOT + col] =
                make_float2(acc[mi][nb][0], acc[mi][nb][1]);
            *(float2*)&g_P[(size_t)(row + 8) * NTOT + col] =
                make_float2(acc[mi][nb][2], acc[mi][nb][3]);
        }
    }
}

// ---------------- parallel: C_t = k_{t-1}.k_t ----------------
__global__ __launch_bounds__(256) void kq_dotsC() {
    const int widx = (blockIdx.x * blockDim.x + threadIdx.x) >> 5;
    if (widx >= MROWS) return;
    const int lane = threadIdx.x & 31;
    const int t = widx / BATCH;
    float kk = 0.f;
    if (t > 0) {
        const float* p  = g_P + (size_t)widx * NTOT;
        const float* pm = g_P + (size_t)(widx - BATCH) * NTOT;
        float2 kt = *(const float2*)&p[2 * lane];
        float2 km = *(const float2*)&pm[2 * lane];
        kk = fmaf(km.x, kt.x, km.y * kt.y);
    }
    #pragma unroll
    for (int o = 1; o < 32; o <<= 1)
        kk += __shfl_xor_sync(0xffffffffu, kk, o);
    if (lane == 0) g_C[widx] = kk;
}

// ---------------- serial recurrence: alpha/w only, branch-free hot loop ----------------
#define RDEPTH 8
#define SSTRIDE 192   // ring stage: k[0..64) v[64..128) a[128..192)

__device__ __forceinline__ float red8(float x) {
    x += __shfl_xor_sync(0xffffffffu, x, 1);
    x += __shfl_xor_sync(0xffffffffu, x, 2);
    x += __shfl_xor_sync(0xffffffffu, x, 4);
    return x;
}
__device__ __forceinline__ float dot4(const ull* a, const ull* b) {
    ull acc = 0;
    #pragma unroll
    for (int j = 0; j < 4; j++) acc = fma2g(a[j], b[j], acc);
    float lo, hi; unpack2(acc, lo, hi);
    return lo + hi;
}

__global__ __launch_bounds__(32, 1) void recur_s(const float* __restrict__ S0,
                                                 const float* __restrict__ dalpha,
                                                 const float* __restrict__ balpha,
                                                 float* __restrict__ Sfinal) {
    const int b = blockIdx.x >> 4;
    const int rw = (blockIdx.x & 15) * 4;
    const int lane = threadIdx.x;
    const int row = rw + (lane >> 3);
    const int c = lane & 7;

    __shared__ __align__(16) float ring[RDEPTH * SSTRIDE];

    ull S2[4];
    {
        const float* sp = S0 + ((size_t)b * NDIM + row) * NDIM + c * 8;
        float4 v0 = *(const float4*)(sp);
        float4 v1 = *(const float4*)(sp + 4);
        S2[0] = pack2(v0.x, v0.y); S2[1] = pack2(v0.z, v0.w);
        S2[2] = pack2(v1.x, v1.y); S2[3] = pack2(v1.z, v1.w);
    }
    const float da = dalpha[row];
    const float ba = balpha[row];

    // prime stages 0..6 — fully uniform across lanes
    #pragma unroll
    for (int p = 0; p < 7; p++) {
        const float* gp = g_P + (size_t)(p * BATCH + b) * NTOT;
        uint32_t sa = smem_u32(&ring[p * SSTRIDE]);
        cpa16(sa + lane * 16, gp + lane * 4);            // k|v : 128 floats
        cpa8(sa + 512 + lane * 8, gp + 192 + lane * 2);  // a   : 64 floats
        cp_commit();
    }

    // C prologue (uniform broadcast loads)
    float Cc = __ldg(&g_C[b]);                 // C_0
    float C1 = __ldg(&g_C[BATCH + b]);         // C_1
    float C2 = __ldg(&g_C[2 * BATCH + b]);     // C_2

    cp_wait<5>();
    __syncwarp();

    // initial U_0 = S_init . k_0
    float Uc;
    {
        float4 a0 = *(const float4*)&ring[c * 8];
        float4 a1 = *(const float4*)&ring[c * 8 + 4];
        ull k0[4] = {pack2(a0.x, a0.y), pack2(a0.z, a0.w),
                     pack2(a1.x, a1.y), pack2(a1.z, a1.w)};
        Uc = red8(dot4(S2, k0));
    }
    float alpha_p = 1.f, w_p = 0.f;

    for (int t = 0; t < T_STEPS; ++t) {
        cp_wait<5>();
        __syncwarp();

        const float* kv0 = &ring[(t & (RDEPTH - 1)) * SSTRIDE];
        const float* kv1 = &ring[((t + 1) & (RDEPTH - 1)) * SSTRIDE];

        // checkpoint every 8 steps (uniform branch): S2 == S_{t-1}
        if ((t & 7) == 0) {
            float* cp = g_CP + (((size_t)(t >> 3) * BATCH + b) * NDIM + row) * NDIM + c * 8;
            *(ulonglong2*)cp = make_ulonglong2(S2[0], S2[1]);
            *(ulonglong2*)(cp + 4) = make_ulonglong2(S2[2], S2[3]);
        }

        // loads (all off the serial chain)
        const float4 kta = *(const float4*)&kv0[c * 8];
        const float4 ktb = *(const float4*)&kv0[c * 8 + 4];
        const float4 kna = *(const float4*)&kv1[c * 8];
        const float4 knb = *(const float4*)&kv1[c * 8 + 4];
        const float vt = kv0[64 + row];
        const float az = kv0[128 + row] + ba;
        int tc = t + 3; tc = (tc < T_STEPS) ? tc : (T_STEPS - 1);   // uniform select
        const float Cnew = __ldg(&g_C[(size_t)tc * BATCH + b]);

        // ---- serial scalar chain (registers only) ----
        const float r1 = fmaf(alpha_p, Uc, w_p * Cc);
        const float z = fmaf(da, r1, az);
        const float e = __expf(-z);
        const float alpha = __fdividef(1.0f, 1.0f + e);
        const float w = fmaf(-vt, alpha, vt);           // (1-alpha)*v

        // alpha/w store: ALL lanes write the identical value (no divergence)
        *(float2*)&g_AW[(size_t)(t * BATCH + b) * NDIM + row] = make_float2(alpha, w);

        // off-chain dot: U_{t+1} = S_{t-1}.k_{t+1}
        ull kn[4] = {pack2(kna.x, kna.y), pack2(kna.z, kna.w),
                     pack2(knb.x, knb.y), pack2(knb.z, knb.w)};
        const float Un = red8(dot4(S2, kn));

        // S update with k_t
        ull kt[4] = {pack2(kta.x, kta.y), pack2(kta.z, kta.w),
                     pack2(ktb.x, ktb.y), pack2(ktb.z, ktb.w)};
        const ull alpha2 = pack2(alpha, alpha);
        const ull w2 = pack2(w, w);
        #pragma unroll
        for (int j = 0; j < 4; j++)
            S2[j] = fma2g(alpha2, S2[j], mul2(w2, kt[j]));

        // prefetch stage t+7 (uniform guard)
        const int tp = t + 7;
        if (tp < T_STEPS) {
            const float* gp = g_P + (size_t)(tp * BATCH + b) * NTOT;
            uint32_t sa = smem_u32(&ring[(tp & (RDEPTH - 1)) * SSTRIDE]);
            cpa16(sa + lane * 16, gp + lane * 4);
            cpa8(sa + 512 + lane * 8, gp + 192 + lane * 2);
        }
        cp_commit();

        // rotate (scalar registers only)
        Uc = Un;
        Cc = C1; C1 = C2; C2 = Cnew;
        alpha_p = alpha; w_p = w;
    }

    if (Sfinal != nullptr) {
        float* sp = Sfinal + ((size_t)b * NDIM + row) * NDIM + c * 8;
        float l0, h0, l1, h1;
        unpack2(S2[0], l0, h0); unpack2(S2[1], l1, h1);
        *(float4*)(sp) = make_float4(l0, h0, l1, h1);
        unpack2(S2[2], l0, h0); unpack2(S2[3], l1, h1);
        *(float4*)(sp + 4) = make_float4(l0, h0, l1, h1);
    }
}

// ---------------- parallel replay: outputs from checkpoints + stored alpha/w ----------------
__global__ __launch_bounds__(256) void out_replay(float* __restrict__ out) {
    const int chunk = blockIdx.x >> 4;
    const int b = blockIdx.x & 15;
    const int tid = threadIdx.x;
    const int row = tid >> 2;
    const int c2 = tid & 3;                  // owns cols [c2*16, c2*16+16)

    __shared__ __align__(16) float kq[8][128];   // k[0..63] | q[64..127] per step
    __shared__ __align__(16) float2 aw[8][NDIM];

    // stage k,q: 1024 floats (4 per thread)
    {
        int i = tid * 4;
        int s = i >> 7, j = i & 127;
        int srcoff = (j < 64) ? j : (64 + j);       // q lives at source offset 128..191
        const float* gp = g_P + (size_t)((chunk * 8 + s) * BATCH + b) * NTOT;
        *(float4*)&kq[s][j] = *(const float4*)(gp + srcoff);
    }
    // stage alpha/w: 512 float2 (2 per thread)
    {
        int i = tid * 2;
        int s = i >> 6, r = i & 63;
        *(float4*)&aw[s][r] =
            *(const float4*)&g_AW[(size_t)((chunk * 8 + s) * BATCH + b) * NDIM + r];
    }

    // load checkpoint state (16 cols per thread)
    ull S2[8];
    {
        const float* cp = g_CP + (((size_t)chunk * BATCH + b) * NDIM + row) * NDIM + c2 * 16;
        #pragma unroll
        for (int j = 0; j < 4; j++) {
            ulonglong2 v = *(const ulonglong2*)(cp + 4 * j);
            S2[2 * j] = v.x; S2[2 * j + 1] = v.y;
        }
    }
    __syncthreads();

    #pragma unroll
    for (int s = 0; s < 8; s++) {
        const float2 awv = aw[s][row];
        ull k2[8], q2[8];
        #pragma unroll
        for (int j = 0; j < 4; j++) {
            float4 kk = *(const float4*)&kq[s][c2 * 16 + 4 * j];
            float4 qq = *(const float4*)&kq[s][64 + c2 * 16 + 4 * j];
            k2[2 * j] = pack2(kk.x, kk.y); k2[2 * j + 1] = pack2(kk.z, kk.w);
            q2[2 * j] = pack2(qq.x, qq.y); q2[2 * j + 1] = pack2(qq.z, qq.w);
        }
        // S update (identical op order to recur_s -> identical S trajectory)
        const ull alpha2 = pack2(awv.x, awv.x);
        const ull w2 = pack2(awv.y, awv.y);
        #pragma unroll
        for (int j = 0; j < 8; j++)
            S2[j] = fma2g(alpha2, S2[j], mul2(w2, k2[j]));
        // out = S_t . q_t, reduced over 4 lanes
        ull a1 = 0, a2 = 0;
        #pragma unroll
        for (int j = 0; j < 4; j++) {
            a1 = fma2g(S2[2 * j], q2[2 * j], a1);
            a2 = fma2g(S2[2 * j + 1], q2[2 * j + 1], a2);
        }
        float x0, x1, y0, y1;
        unpack2(a1, x0, x1); unpack2(a2, y0, y1);
        float d = (x0 + y0) + (x1 + y1);
        d += __shfl_xor_sync(0xffffffffu, d, 1);
        d += __shfl_xor_sync(0xffffffffu, d, 2);
        const float eo = __expf(-d);
        const float res = d * d * __fdividef(1.0f, 1.0f + eo);
        if (c2 == 0)
            out[(size_t)((chunk * 8 + s) * BATCH + b) * NDIM + row] = res;
    }
}

// ---------------- launch ----------------
extern "C" void kernel_launch(void* const* d_in, const int* in_sizes, int n_in,
                              void* d_out, int out_size) {
    const float* x  = (const float*)d_in[0];
    const float* S0 = (const float*)d_in[1];
    const float* Wk = (const float*)d_in[2];
    const float* Wv = (const float*)d_in[3];
    const float* Wq = (const float*)d_in[4];
    const float* Wa = (const float*)d_in[5];
    const float* da = (const float*)d_in[6];
    const float* ba = (const float*)d_in[7];

    float* out = (float*)d_out;
    const int out_elems = T_STEPS * BATCH * NDIM;
    const int sf_elems  = BATCH * NDIM * NDIM;
    float* Sf = (out_size >= out_elems + sf_elems) ? (out + out_elems) : nullptr;

    const int smem_bytes = NSTAGE * STAGE_ELE * 2;   // 122880
    cudaFuncSetAttribute(gemm_mma, cudaFuncAttributeMaxDynamicSharedMemorySize, smem_bytes);

    convert_x<<<2048, 256>>>(x);
    convert_w<<<NTOT, 256>>>(Wk, Wv, Wq, Wa);

    dim3 ggrid(NTOT / BN, MROWS / BM);   // (2, 256)
    gemm_mma<<<ggrid, 256, smem_bytes>>>(0);

    kq_dotsC<<<MROWS / 8, 256>>>();
    recur_s<<<BATCH * 16, 32>>>(S0, da, ba, Sf);
    out_replay<<<NCHUNKS * BATCH, 256>>>(out);
}

// round 15
// speedup vs baseline: 2.9475x; 2.9475x over previous
#include <cuda_runtime.h>
#include <cuda_bf16.h>
#include <cstdint>

#define T_STEPS 2048
#define BATCH   16
#define DIM     1024
#define NDIM    64
#define NTOT    256
#define MROWS   (T_STEPS * BATCH)   // 32768

// ---------------- static device scratch ----------------
__device__ __nv_bfloat16 g_Ah[MROWS * DIM];
__device__ __nv_bfloat16 g_Al[MROWS * DIM];
__device__ __nv_bfloat16 g_Bh[NTOT * DIM];    // [n][k]
__device__ __nv_bfloat16 g_Bl[NTOT * DIM];
__device__ float g_P[MROWS * NTOT];           // [t*B+b][k|v|q|a]

// ---------------- PTX helpers (baseline ISA only) ----------------
__device__ __forceinline__ uint32_t smem_u32(const void* p) {
    return (uint32_t)__cvta_generic_to_shared(p);
}
__device__ __forceinline__ void cpa16(uint32_t sa, const void* g) {
    asm volatile("cp.async.cg.shared.global [%0], [%1], 16;" :: "r"(sa), "l"(g) : "memory");
}
__device__ __forceinline__ void cp_commit() {
    asm volatile("cp.async.commit_group;" ::: "memory");
}
template<int N>
__device__ __forceinline__ void cp_wait() {
    asm volatile("cp.async.wait_group %0;" :: "n"(N) : "memory");
}
__device__ __forceinline__ void ldm_x4(uint32_t& r0, uint32_t& r1, uint32_t& r2, uint32_t& r3,
                                       uint32_t addr) {
    asm volatile("ldmatrix.sync.aligned.m8n8.x4.shared.b16 {%0,%1,%2,%3}, [%4];"
                 : "=r"(r0), "=r"(r1), "=r"(r2), "=r"(r3) : "r"(addr));
}
__device__ __forceinline__ void mma_bf16(float* c, const uint32_t* a, const uint32_t* b) {
    asm volatile("mma.sync.aligned.m16n8k16.row.col.f32.bf16.bf16.f32 "
                 "{%0,%1,%2,%3}, {%4,%5,%6,%7}, {%8,%9}, {%0,%1,%2,%3};"
                 : "+f"(c[0]), "+f"(c[1]), "+f"(c[2]), "+f"(c[3])
                 : "r"(a[0]), "r"(a[1]), "r"(a[2]), "r"(a[3]), "r"(b[0]), "r"(b[1]));
}

// packed f32x2
typedef unsigned long long ull;
__device__ __forceinline__ ull pack2(float lo, float hi) {
    ull r; asm("mov.b64 %0, {%1, %2};" : "=l"(r) : "f"(lo), "f"(hi)); return r;
}
__device__ __forceinline__ void unpack2(ull v, float& lo, float& hi) {
    asm("mov.b64 {%0, %1}, %2;" : "=f"(lo), "=f"(hi) : "l"(v));
}
__device__ __forceinline__ ull fma2g(ull a, ull b, ull c) {
    ull d; asm("fma.rn.f32x2 %0, %1, %2, %3;" : "=l"(d) : "l"(a), "l"(b), "l"(c)); return d;
}
__device__ __forceinline__ ull mul2(ull a, ull b) {
    ull d; asm("mul.rn.f32x2 %0, %1, %2;" : "=l"(d) : "l"(a), "l"(b)); return d;
}

__device__ __forceinline__ void split_bf16(float x, __nv_bfloat16& h, __nv_bfloat16& l) {
    h = __float2bfloat16(x);
    l = __float2bfloat16(x - __bfloat162float(h));
}

// ---------------- prep kernels ----------------
__global__ void convert_x(const float* __restrict__ x) {
    const int total4 = MROWS * DIM / 4;
    for (int i = blockIdx.x * blockDim.x + threadIdx.x; i < total4;
         i += gridDim.x * blockDim.x) {
        float4 v = ((const float4*)x)[i];
        __nv_bfloat16 h0, h1, h2, h3, l0, l1, l2, l3;
        split_bf16(v.x, h0, l0); split_bf16(v.y, h1, l1);
        split_bf16(v.z, h2, l2); split_bf16(v.w, h3, l3);
        ((__nv_bfloat162*)g_Ah)[2 * i + 0] = __nv_bfloat162(h0, h1);
        ((__nv_bfloat162*)g_Ah)[2 * i + 1] = __nv_bfloat162(h2, h3);
        ((__nv_bfloat162*)g_Al)[2 * i + 0] = __nv_bfloat162(l0, l1);
        ((__nv_bfloat162*)g_Al)[2 * i + 1] = __nv_bfloat162(l2, l3);
    }
}

__global__ void convert_w(const float* __restrict__ Wk, const float* __restrict__ Wv,
                          const float* __restrict__ Wq, const float* __restrict__ Wa) {
    int n = blockIdx.x;
    int g = n >> 6, r = n & 63;
    const float* W = (g == 0) ? Wk : (g == 1) ? Wv : (g == 2) ? Wq : Wa;
    for (int d = threadIdx.x; d < DIM; d += blockDim.x) {
        __nv_bfloat16 h, l;
        split_bf16(W[r * DIM + d], h, l);
        g_Bh[n * DIM + d] = h;
        g_Bl[n * DIM + d] = l;
    }
}

// ---------------- mma.sync GEMM (identical to R6) ----------------
#define BM 128
#define BN 128
#define BK 32
#define LDP 40
#define KT (DIM / BK)
#define NSTAGE 3
#define STAGE_ELE (4 * 128 * LDP)

__device__ __forceinline__ uint32_t soff(int stage, int arr, int row, int col) {
    return (uint32_t)(((stage * STAGE_ELE) + ((arr * 128 + row) * LDP) + col) * 2);
}

__global__ __launch_bounds__(256, 1) void gemm_mma(int unused) {
    extern __shared__ __nv_bfloat16 smem[];
    const uint32_t sbase = smem_u32(smem);

    const int m0 = blockIdx.y * BM;
    const int n0 = blockIdx.x * BN;
    const int tid = threadIdx.x;
    const int wid = tid >> 5;
    const int lane = tid & 31;
    const int warp_m = (wid & 3) * 32;
    const int warp_n = (wid >> 2) * 64;

    float acc[2][8][4];
    #pragma unroll
    for (int i = 0; i < 2; i++)
        #pragma unroll
        for (int j = 0; j < 8; j++)
            #pragma unroll
            for (int r = 0; r < 4; r++) acc[i][j][r] = 0.f;

    const int lm = lane >> 3;
    const int arow = (lm & 1) * 8 + (lane & 7);
    const int akc  = (lm >> 1) * 8;
    const int bnof = (lm >> 1) * 8 + (lane & 7);
    const int bkc  = (lm & 1) * 8;

    auto load_stage = [&](int stage, int kt) {
        const int k0 = kt * BK;
        #pragma unroll
        for (int arr = 0; arr < 4; arr++) {
            const __nv_bfloat16* gb = (arr == 0) ? g_Ah : (arr == 1) ? g_Al
                                   : (arr == 2) ? g_Bh : g_Bl;
            const int rbase = (arr < 2) ? m0 : n0;
            #pragma unroll
            for (int h = 0; h < 2; h++) {
                int cl = h * 256 + tid;
                int row = cl >> 2;
                int seg = cl & 3;
                cpa16(sbase + soff(stage, arr, row, seg * 8),
                      gb + (size_t)(rbase + row) * DIM + k0 + seg * 8);
            }
        }
        cp_commit();
    };

    load_stage(0, 0);
    load_stage(1, 1);

    int cur = 0;
    for (int kt = 0; kt < KT; ++kt) {
        if (kt + 2 < KT) {
            load_stage((kt + 2) % NSTAGE, kt + 2);
            cp_wait<2>();
        } else if (kt + 1 < KT) {
            cp_wait<1>();
        } else {
            cp_wait<0>();
        }
        __syncthreads();

        #pragma unroll
        for (int kk = 0; kk < BK; kk += 16) {
            uint32_t ah[2][4], al[2][4], bh[8][2], bl[8][2];
            #pragma unroll
            for (int mi = 0; mi < 2; mi++) {
                ldm_x4(ah[mi][0], ah[mi][1], ah[mi][2], ah[mi][3],
                       sbase + soff(cur, 0, warp_m + mi * 16 + arow, kk + akc));
                ldm_x4(al[mi][0], al[mi][1], al[mi][2], al[mi][3],
                       sbase + soff(cur, 1, warp_m + mi * 16 + arow, kk + akc));
            }
            #pragma unroll
            for (int p = 0; p < 4; p++) {
                ldm_x4(bh[2 * p][0], bh[2 * p][1], bh[2 * p + 1][0], bh[2 * p + 1][1],
                       sbase + soff(cur, 2, warp_n + p * 16 + bnof, kk + bkc));
                ldm_x4(bl[2 * p][0], bl[2 * p][1], bl[2 * p + 1][0], bl[2 * p + 1][1],
                       sbase + soff(cur, 3, warp_n + p * 16 + bnof, kk + bkc));
            }
            #pragma unroll
            for (int mi = 0; mi < 2; mi++)
                #pragma unroll
                for (int nb = 0; nb < 8; nb++) {
                    mma_bf16(acc[mi][nb], ah[mi], bh[nb]);
                    mma_bf16(acc[mi][nb], ah[mi], bl[nb]);
                    mma_bf16(acc[mi][nb], al[mi], bh[nb]);
                }
        }
        __syncthreads();
        cur = (cur + 1) % NSTAGE;
    }

    const int cr = lane >> 2;
    const int cc = (lane & 3) * 2;
    #pragma unroll
    for (int mi = 0; mi < 2; mi++) {
        #pragma unroll
        for (int nb = 0; nb < 8; nb++) {
            int row = m0 + warp_m + mi * 16 + cr;
            int col = n0 + warp_n + nb * 8 + cc;
            *(float2*)&g_P[(size_t)row * NTOT + col] =
                make_float2(acc[mi][nb][0], acc[mi][nb][1]);
            *(float2*)&g_P[(size_t)(row + 8) * NTOT + col] =
                make_float2(acc[mi][nb][2], acc[mi][nb][3]);
        }
    }
}

// ---------------- recurrence: R6 algorithm, branchless output + ping-pong unroll ----------------
#define RDEPTH 8

__device__ __forceinline__ float red8(float x) {
    x += __shfl_xor_sync(0xffffffffu, x, 1);
    x += __shfl_xor_sync(0xffffffffu, x, 2);
    x += __shfl_xor_sync(0xffffffffu, x, 4);
    return x;
}
__device__ __forceinline__ float dot4(const ull* a, const ull* b) {
    ull acc = 0;
    #pragma unroll
    for (int j = 0; j < 4; j++) acc = fma2g(a[j], b[j], acc);
    float lo, hi; unpack2(acc, lo, hi);
    return lo + hi;
}

__global__ __launch_bounds__(32, 1) void recur_w(const float* __restrict__ S0,
                                                 const float* __restrict__ dalpha,
                                                 const float* __restrict__ balpha,
                                                 float* __restrict__ out,
                                                 float* __restrict__ Sfinal) {
    const int b = blockIdx.x >> 4;           // batch
    const int rw = (blockIdx.x & 15) * 4;    // first row of this warp
    const int lane = threadIdx.x;
    const int row = rw + (lane >> 3);        // global row (0..63)
    const int c = lane & 7;                  // col chunk: cols [c*8, c*8+8)

    __shared__ __align__(16) float ring[RDEPTH][NTOT];

    ull S2[4];
    {
        const float* sp = S0 + ((size_t)b * NDIM + row) * NDIM + c * 8;
        float4 v0 = *(const float4*)(sp);
        float4 v1 = *(const float4*)(sp + 4);
        S2[0] = pack2(v0.x, v0.y); S2[1] = pack2(v0.z, v0.w);
        S2[2] = pack2(v1.x, v1.y); S2[3] = pack2(v1.z, v1.w);
    }
    const float da = dalpha[row];
    const float ba = balpha[row];

    // prime ring stages 0..6
    #pragma unroll
    for (int p = 0; p < 7; p++) {
        const float* gp = g_P + (size_t)(p * BATCH + b) * NTOT;
        uint32_t sa = smem_u32(&ring[p][lane * 8]);
        cpa16(sa, gp + lane * 8);
        cpa16(sa + 16, gp + lane * 8 + 4);
        cp_commit();
    }
    cp_wait<6>();
    __syncwarp();

    // ping-pong buffers: index 0 / 1 by literal
    ull kbuf[2][4], qbuf[2][4];
    float vv[2], aa[2];
    {
        const float* kv = ring[0];
        float4 k0 = *(const float4*)&kv[c * 8];
        float4 k1 = *(const float4*)&kv[c * 8 + 4];
        float4 q0 = *(const float4*)&kv[2 * NDIM + c * 8];
        float4 q1 = *(const float4*)&kv[2 * NDIM + c * 8 + 4];
        kbuf[0][0] = pack2(k0.x, k0.y); kbuf[0][1] = pack2(k0.z, k0.w);
        kbuf[0][2] = pack2(k1.x, k1.y); kbuf[0][3] = pack2(k1.z, k1.w);
        qbuf[0][0] = pack2(q0.x, q0.y); qbuf[0][1] = pack2(q0.z, q0.w);
        qbuf[0][2] = pack2(q1.x, q1.y); qbuf[0][3] = pack2(q1.z, q1.w);
        vv[0] = kv[NDIM + row];
        aa[0] = kv[3 * NDIM + row];
    }

    float Uc = red8(dot4(S2, kbuf[0]));   // S_init . k_0
    float Cc = 0.f;
    float alpha_p = 1.f, w_p = 0.f;

    // one recurrence step; CUR/NXT are literal 0/1 (ping-pong, no register rotation)
#define STEP_BODY(T, CUR, NXT)                                                          \
    {                                                                                   \
        cp_wait<5>();                                                                   \
        __syncwarp();                                                                   \
        const int tn = ((T) + 1 < T_STEPS) ? ((T) + 1) : (T);                           \
        const float* kv = ring[tn & (RDEPTH - 1)];                                      \
        {                                                                               \
            float4 k0 = *(const float4*)&kv[c * 8];                                     \
            float4 k1 = *(const float4*)&kv[c * 8 + 4];                                 \
            float4 q0 = *(const float4*)&kv[2 * NDIM + c * 8];                          \
            float4 q1 = *(const float4*)&kv[2 * NDIM + c * 8 + 4];                      \
            kbuf[NXT][0] = pack2(k0.x, k0.y); kbuf[NXT][1] = pack2(k0.z, k0.w);         \
            kbuf[NXT][2] = pack2(k1.x, k1.y); kbuf[NXT][3] = pack2(k1.z, k1.w);         \
            qbuf[NXT][0] = pack2(q0.x, q0.y); qbuf[NXT][1] = pack2(q0.z, q0.w);         \
            qbuf[NXT][2] = pack2(q1.x, q1.y); qbuf[NXT][3] = pack2(q1.z, q1.w);         \
            vv[NXT] = kv[NDIM + row];                                                   \
            aa[NXT] = kv[3 * NDIM + row];                                               \
        }                                                                               \
        const float r1 = fmaf(alpha_p, Uc, w_p * Cc);                                   \
        const float z = fmaf(da, r1, aa[CUR] + ba);                                     \
        const float e = __expf(-z);                                                     \
        const float alpha = __fdividef(1.0f, 1.0f + e);                                 \
        const float w = fmaf(-vv[CUR], alpha, vv[CUR]);                                 \
        const float Un = red8(dot4(S2, kbuf[NXT]));                                     \
        const float Cn = red8(dot4(kbuf[CUR], kbuf[NXT]));                              \
        const float R2 = red8(dot4(S2, qbuf[CUR]));                                     \
        const float E2 = red8(dot4(kbuf[CUR], qbuf[CUR]));                              \
        const ull alpha2 = pack2(alpha, alpha);                                         \
        const ull w2 = pack2(w, w);                                                     \
        _Pragma("unroll")                                                               \
        for (int j = 0; j < 4; j++)                                                     \
            S2[j] = fma2g(alpha2, S2[j], mul2(w2, kbuf[CUR][j]));                       \
        /* branchless output: warp-wide compute, predicated single store */             \
        const float o = fmaf(alpha, R2, w * E2);                                        \
        const float eo = __expf(-o);                                                    \
        const float res = o * o * __fdividef(1.0f, 1.0f + eo);                          \
        if (c == 0)                                                                     \
            out[((size_t)(T) * BATCH + b) * NDIM + row] = res;                          \
        const int tp = (T) + 7;                                                         \
        if (tp < T_STEPS) {                                                             \
            const float* gp = g_P + (size_t)(tp * BATCH + b) * NTOT;                    \
            uint32_t sa = smem_u32(&ring[tp & (RDEPTH - 1)][lane * 8]);                 \
            cpa16(sa, gp + lane * 8);                                                   \
            cpa16(sa + 16, gp + lane * 8 + 4);                                          \
        }                                                                               \
        cp_commit();                                                                    \
        Uc = Un; Cc = Cn; alpha_p = alpha; w_p = w;                                     \
    }

    for (int t = 0; t < T_STEPS; t += 2) {
        STEP_BODY(t, 0, 1);
        STEP_BODY(t + 1, 1, 0);
    }
#undef STEP_BODY

    if (Sfinal != nullptr) {
        float* sp = Sfinal + ((size_t)b * NDIM + row) * NDIM + c * 8;
        float l0, h0, l1, h1;
        unpack2(S2[0], l0, h0); unpack2(S2[1], l1, h1);
        *(float4*)(sp) = make_float4(l0, h0, l1, h1);
        unpack2(S2[2], l0, h0); unpack2(S2[3], l1, h1);
        *(float4*)(sp + 4) = make_float4(l0, h0, l1, h1);
    }
}

// ---------------- launch ----------------
extern "C" void kernel_launch(void* const* d_in, const int* in_sizes, int n_in,
                              void* d_out, int out_size) {
    const float* x  = (const float*)d_in[0];
    const float* S0 = (const float*)d_in[1];
    const float* Wk = (const float*)d_in[2];
    const float* Wv = (const float*)d_in[3];
    const float* Wq = (const float*)d_in[4];
    const float* Wa = (const float*)d_in[5];
    const float* da = (const float*)d_in[6];
    const float* ba = (const float*)d_in[7];

    float* out = (float*)d_out;
    const int out_elems = T_STEPS * BATCH * NDIM;
    const int sf_elems  = BATCH * NDIM * NDIM;
    float* Sf = (out_size >= out_elems + sf_elems) ? (out + out_elems) : nullptr;

    const int smem_bytes = NSTAGE * STAGE_ELE * 2;   // 122880
    cudaFuncSetAttribute(gemm_mma, cudaFuncAttributeMaxDynamicSharedMemorySize, smem_bytes);

    convert_x<<<2048, 256>>>(x);
    convert_w<<<NTOT, 256>>>(Wk, Wv, Wq, Wa);

    dim3 ggrid(NTOT / BN, MROWS / BM);   // (2, 256)
    gemm_mma<<<ggrid, 256, smem_bytes>>>(0);

    recur_w<<<BATCH * 16, 32>>>(S0, da, ba, out, Sf);
}